// round 14
// baseline (speedup 1.0000x reference)
#include <cuda_runtime.h>
#include <cuda_fp16.h>
#include <math.h>
#include <stdint.h>

// Problem constants
#define BB   64
#define TT   8
#define DD   512
#define SS   512
#define NKVH 4
#define QK_SCALE 0.044194173824159216f
#define EPS 1e-6f

// ---------------------------------------------------------------------------
// Device-global scratch
// ---------------------------------------------------------------------------
__device__ float g_q[BB * TT * DD];          // raw q projection
__device__ float g_qn[BB * TT * DD];         // normalized q * (1+qw)(1+kw)
__device__ float g_qt[BB * TT * DD];         // q-tilde
__device__ float g_sumsq2[2][BB * NKVH * SS];// sumsq partials (etile-pair halves)
__device__ float g_sc[BB * TT * SS];         // scores, then attn
__device__ float g_ctxp[4][BB * TT * DD];    // ctx partials per stile
__device__ int   g_mask_mode;
__device__ __half g_hH[BB * SS * DD];        // hist fp16
__device__ __half g_wH[NKVH * DD * DD];      // Wk fp16
__device__ float  g_gram[NKVH * DD * DD];    // G = W^T W (fp32)
__device__ __half g_bu[NKVH * DD * DD];      // U = triu(G), half diag, fp16

// ---------------------------------------------------------------------------
// PTX helpers
// ---------------------------------------------------------------------------
__device__ __forceinline__ uint32_t smem_u32(const void* p) {
    uint32_t a;
    asm("{ .reg .u64 t; cvta.to.shared.u64 t, %1; cvt.u32.u64 %0, t; }"
        : "=r"(a) : "l"(p));
    return a;
}
__device__ __forceinline__ void cp_async16(uint32_t dst, const void* src) {
    asm volatile("cp.async.cg.shared.global [%0], [%1], 16;"
                 :: "r"(dst), "l"(src));
}
#define CPASYNC_COMMIT() asm volatile("cp.async.commit_group;" ::: "memory")
#define CPASYNC_WAIT2()  asm volatile("cp.async.wait_group 2;" ::: "memory")
#define CPASYNC_WAIT1()  asm volatile("cp.async.wait_group 1;" ::: "memory")
#define CPASYNC_WAIT0()  asm volatile("cp.async.wait_group 0;" ::: "memory")

__device__ __forceinline__ void ldmatrix_x4(uint32_t& r0, uint32_t& r1,
                                            uint32_t& r2, uint32_t& r3,
                                            uint32_t addr) {
    asm volatile("ldmatrix.sync.aligned.m8n8.x4.shared.b16 {%0,%1,%2,%3}, [%4];"
                 : "=r"(r0), "=r"(r1), "=r"(r2), "=r"(r3) : "r"(addr));
}
__device__ __forceinline__ void mma_fp16(float* d, const uint32_t* a,
                                         const uint32_t* b) {
    asm volatile(
        "mma.sync.aligned.m16n8k16.row.col.f32.f16.f16.f32 "
        "{%0,%1,%2,%3}, {%4,%5,%6,%7}, {%8,%9}, {%0,%1,%2,%3};"
        : "+f"(d[0]), "+f"(d[1]), "+f"(d[2]), "+f"(d[3])
        : "r"(a[0]), "r"(a[1]), "r"(a[2]), "r"(a[3]), "r"(b[0]), "r"(b[1]));
}

// ---------------------------------------------------------------------------
// Mask dtype sniffer
// ---------------------------------------------------------------------------
__global__ void k_detect_mask(const unsigned int* __restrict__ m) {
    __shared__ int flags[3];
    int tid = threadIdx.x;
    if (tid < 3) flags[tid] = 1;
    __syncthreads();
    int iok = 1, fok = 1, hok = 1;
    for (int i = tid; i < 8192; i += blockDim.x) {
        unsigned w = m[i];
        if (w > 1u) iok = 0;
        float f = __uint_as_float(w);
        if (!(f == 0.0f || f == 1.0f)) fok = 0;
        unsigned lo = w & 0xFFFFu, hi = w >> 16;
        if (!((lo == 0u || lo == 0x3F80u) && (hi == 0u || hi == 0x3F80u))) hok = 0;
    }
    if (!iok) atomicExch(&flags[0], 0);
    if (!fok) atomicExch(&flags[1], 0);
    if (!hok) atomicExch(&flags[2], 0);
    __syncthreads();
    if (tid == 0)
        g_mask_mode = flags[0] ? 0 : (flags[1] ? 1 : (flags[2] ? 3 : 2));
}
__device__ __forceinline__ bool is_masked(const void* m, int idx, int mode) {
    if (mode == 0) return ((const int*)m)[idx] != 0;
    if (mode == 1) return ((const float*)m)[idx] != 0.0f;
    if (mode == 3) return ((const unsigned short*)m)[idx] != 0;
    return ((const unsigned char*)m)[idx] != 0;
}

// ---------------------------------------------------------------------------
// fp32 -> fp16 conversion
// ---------------------------------------------------------------------------
__global__ void k_tofp16(const float* __restrict__ src,
                         __half* __restrict__ dst, int n4) {
    int i = blockIdx.x * blockDim.x + threadIdx.x;
    int stride = gridDim.x * blockDim.x;
    for (; i < n4; i += stride) {
        float4 v = ((const float4*)src)[i];
        ((__half2*)dst)[i * 2 + 0] = __floats2half2_rn(v.x, v.y);
        ((__half2*)dst)[i * 2 + 1] = __floats2half2_rn(v.z, v.w);
    }
}

// ---------------------------------------------------------------------------
// Gram: G[n][d1][d2] = sum_e W[e,d1] * W[e,d2]  (HMMA, transposed smem staging)
// grid 64 = n(4) x t1(4) x t2(4), 256 thr, CTA tile 128x128, K=512 in 16 chunks.
// ---------------------------------------------------------------------------
#define GR_ROWB 80
#define GR_ATILE (128 * GR_ROWB)   // 10240

__global__ void __launch_bounds__(256) k_gram() {
    __shared__ __align__(16) char smem[2 * GR_ATILE];
    uint32_t sbase = smem_u32(smem);
    int tid = threadIdx.x;
    int wid = tid >> 5, lane = tid & 31;
    int warp_m = wid & 3;
    int warp_n = wid >> 2;

    int t2 = blockIdx.x & 3;
    int t1 = (blockIdx.x >> 2) & 3;
    int n  = blockIdx.x >> 4;
    const __half* W = g_wH + (size_t)n * DD * DD;

    int g = lane >> 3, lr = lane & 7;
    int a_row16 = ((g & 1) << 3) + lr;
    int a_kc = g >> 1;
    uint32_t a_off0 = (uint32_t)((warp_m * 32 + a_row16) * GR_ROWB + a_kc * 16);
    uint32_t a_off1 = a_off0 + 16 * GR_ROWB;
    int b_row16 = ((g >> 1) << 3) + lr;
    int b_kc = g & 1;
    uint32_t b_off[4];
#pragma unroll
    for (int p = 0; p < 4; p++)
        b_off[p] = (uint32_t)(GR_ATILE +
                   (warp_n * 64 + p * 16 + b_row16) * GR_ROWB + b_kc * 16);

    float acc[2][8][4];
#pragma unroll
    for (int mt = 0; mt < 2; mt++)
#pragma unroll
        for (int nt = 0; nt < 8; nt++)
#pragma unroll
            for (int c = 0; c < 4; c++) acc[mt][nt][c] = 0.0f;

    for (int j = 0; j < 16; j++) {
        int e0 = j * 32;
        __syncthreads();
        // transposed staging: read W rows [e][d..d+7], write smem[d][e]
#pragma unroll
        for (int it = 0; it < 2; it++) {
            int item = tid + it * 256;
            int er = item >> 4;      // 0..31
            int db = item & 15;      // 0..15 -> d-offset db*8
            uint4 va = *(const uint4*)(W + (size_t)(e0 + er) * DD + t1 * 128 + db * 8);
            uint4 vb = *(const uint4*)(W + (size_t)(e0 + er) * DD + t2 * 128 + db * 8);
            const __half* ha = (const __half*)&va;
            const __half* hb = (const __half*)&vb;
#pragma unroll
            for (int i = 0; i < 8; i++) {
                *(__half*)(smem + (db * 8 + i) * GR_ROWB + er * 2) = ha[i];
                *(__half*)(smem + GR_ATILE + (db * 8 + i) * GR_ROWB + er * 2) = hb[i];
            }
        }
        __syncthreads();
#pragma unroll
        for (int ks = 0; ks < 2; ks++) {
            uint32_t koff = (uint32_t)(ks * 32);
            uint32_t afrag[2][4];
            uint32_t bfrag[8][2];
            ldmatrix_x4(afrag[0][0], afrag[0][1], afrag[0][2], afrag[0][3],
                        sbase + a_off0 + koff);
            ldmatrix_x4(afrag[1][0], afrag[1][1], afrag[1][2], afrag[1][3],
                        sbase + a_off1 + koff);
#pragma unroll
            for (int p = 0; p < 4; p++) {
                ldmatrix_x4(bfrag[2 * p][0], bfrag[2 * p][1],
                            bfrag[2 * p + 1][0], bfrag[2 * p + 1][1],
                            sbase + b_off[p] + koff);
            }
#pragma unroll
            for (int mt = 0; mt < 2; mt++)
#pragma unroll
                for (int nt = 0; nt < 8; nt++)
                    mma_fp16(acc[mt][nt], afrag[mt], bfrag[nt]);
        }
    }

    float* Gn = g_gram + (size_t)n * DD * DD;
#pragma unroll
    for (int mt = 0; mt < 2; mt++)
#pragma unroll
        for (int nt = 0; nt < 8; nt++) {
            int r = t1 * 128 + warp_m * 32 + mt * 16 + (lane >> 2);
            int c = t2 * 128 + warp_n * 64 + nt * 8 + (lane & 3) * 2;
            float2 lo = make_float2(acc[mt][nt][0], acc[mt][nt][1]);
            float2 hi = make_float2(acc[mt][nt][2], acc[mt][nt][3]);
            *(float2*)&Gn[(size_t)r * DD + c] = lo;
            *(float2*)&Gn[(size_t)(r + 8) * DD + c] = hi;
        }
}

// ---------------------------------------------------------------------------
// Build U = triu(G) with halved diagonal, fp16.  1M halves / 2 per thread.
// ---------------------------------------------------------------------------
__global__ void k_build_u() {
    int idx = blockIdx.x * blockDim.x + threadIdx.x;   // 0..524287
    int d2 = (idx & 255) * 2;
    int d1 = (idx >> 8) & 511;
    int n = idx >> 17;
    size_t base = (size_t)n * DD * DD + (size_t)d1 * DD + d2;
    float g0 = g_gram[base], g1 = g_gram[base + 1];
    float u0 = (d2 > d1) ? g0 : ((d2 == d1) ? 0.5f * g0 : 0.0f);
    float u1 = (d2 + 1 > d1) ? g1 : ((d2 + 1 == d1) ? 0.5f * g1 : 0.0f);
    *(__half2*)&g_bu[base] = __floats2half2_rn(u0, u1);
}

// ---------------------------------------------------------------------------
// Raw Q projection: coalesced tiled SGEMM, 64x64 tiles, double-buffered.
// ---------------------------------------------------------------------------
__global__ void __launch_bounds__(256) k_qproj_gemm(const float* __restrict__ tgt,
                                                    const float* __restrict__ Wq) {
    __shared__ float As[2][16][68];
    __shared__ float Bs[2][16][68];
    int tid = threadIdx.x;
    int m0 = (blockIdx.x >> 3) * 64;
    int e0 = (blockIdx.x & 7) * 64;

    int lrow = tid >> 2;
    int lkc  = (tid & 3) * 4;
    int trow = tid >> 4;
    int tcol = tid & 15;

    float acc[4][4];
#pragma unroll
    for (int i = 0; i < 4; i++)
#pragma unroll
        for (int j = 0; j < 4; j++) acc[i][j] = 0.0f;

    float4 ra = *(const float4*)(tgt + (size_t)(m0 + lrow) * DD + lkc);
    float4 rb = *(const float4*)(Wq  + (size_t)(e0 + lrow) * DD + lkc);
#pragma unroll
    for (int j = 0; j < 4; j++) {
        As[0][lkc + j][lrow] = ((const float*)&ra)[j];
        Bs[0][lkc + j][lrow] = ((const float*)&rb)[j];
    }
    __syncthreads();

    for (int s = 0; s < 32; s++) {
        int buf = s & 1;
        if (s + 1 < 32) {
            int k0 = (s + 1) * 16;
            ra = *(const float4*)(tgt + (size_t)(m0 + lrow) * DD + k0 + lkc);
            rb = *(const float4*)(Wq  + (size_t)(e0 + lrow) * DD + k0 + lkc);
        }
#pragma unroll
        for (int k = 0; k < 16; k++) {
            float ar[4], br[4];
            *(float4*)ar = *(const float4*)&As[buf][k][trow * 4];
            *(float4*)br = *(const float4*)&Bs[buf][k][tcol * 4];
#pragma unroll
            for (int i = 0; i < 4; i++)
#pragma unroll
                for (int j = 0; j < 4; j++) acc[i][j] += ar[i] * br[j];
        }
        if (s + 1 < 32) {
            __syncthreads();
#pragma unroll
            for (int j = 0; j < 4; j++) {
                As[buf ^ 1][lkc + j][lrow] = ((const float*)&ra)[j];
                Bs[buf ^ 1][lkc + j][lrow] = ((const float*)&rb)[j];
            }
            __syncthreads();
        }
    }
#pragma unroll
    for (int i = 0; i < 4; i++)
        *(float4*)&g_q[(size_t)(m0 + trow * 4 + i) * DD + e0 + tcol * 4] =
            *(float4*)acc[i];
}

// ---------------------------------------------------------------------------
// Q RMS-norm: one warp per row; qn = q*inv_rms*(1+qw)*(1+kw)
// ---------------------------------------------------------------------------
__global__ void __launch_bounds__(256) k_qnorm(const float* __restrict__ qw,
                                               const float* __restrict__ kw) {
    int wid = threadIdx.x >> 5, lane = threadIdx.x & 31;
    int row = blockIdx.x * 8 + wid;
    const float4* src = (const float4*)(g_q + (size_t)row * DD);
    float4 v[4];
    float ss = 0.0f;
#pragma unroll
    for (int j = 0; j < 4; j++) {
        v[j] = src[lane + 32 * j];
        ss += v[j].x * v[j].x + v[j].y * v[j].y + v[j].z * v[j].z + v[j].w * v[j].w;
    }
#pragma unroll
    for (int off = 16; off > 0; off >>= 1)
        ss += __shfl_xor_sync(0xFFFFFFFFu, ss, off);
    float inv = rsqrtf(ss * (1.0f / (float)DD) + EPS);
    float4* dst = (float4*)(g_qn + (size_t)row * DD);
#pragma unroll
    for (int j = 0; j < 4; j++) {
        int e4 = (lane + 32 * j) * 4;
        float4 wq = *(const float4*)(qw + e4);
        float4 wk = *(const float4*)(kw + e4);
        float4 o;
        o.x = v[j].x * inv * (1.0f + wq.x) * (1.0f + wk.x);
        o.y = v[j].y * inv * (1.0f + wq.y) * (1.0f + wk.y);
        o.z = v[j].z * inv * (1.0f + wq.z) * (1.0f + wk.z);
        o.w = v[j].w * inv * (1.0f + wq.w) * (1.0f + wk.w);
        dst[lane + 32 * j] = o;
    }
}

// ---------------------------------------------------------------------------
// q-tilde GEMM: qt[m,d] = sum_e qn[m,e] * Wk[n*D+e, d] * SCALE
// ---------------------------------------------------------------------------
__global__ void __launch_bounds__(256) k_qtilde_gemm(const float* __restrict__ Wk) {
    __shared__ float As[2][16][68];
    __shared__ float Bs[2][16][68];
    int tid = threadIdx.x;
    int n  = blockIdx.x >> 4;
    int mt = (blockIdx.x >> 3) & 1;
    int nt = blockIdx.x & 7;
    int m0 = mt * 64;
    int d0 = nt * 64;

    auto grow = [&](int m) { return (m >> 1) * TT + n * 2 + (m & 1); };

    int lrow = tid >> 2;
    int lkc  = (tid & 3) * 4;
    int bkr  = tid >> 4;
    int bn4  = (tid & 15) * 4;
    int trow = tid >> 4;
    int tcol = tid & 15;

    size_t arow_off = (size_t)grow(m0 + lrow) * DD;
    const float* wbase = Wk + (size_t)n * DD * DD + d0;

    float acc[4][4];
#pragma unroll
    for (int i = 0; i < 4; i++)
#pragma unroll
        for (int j = 0; j < 4; j++) acc[i][j] = 0.0f;

    float4 ra = *(const float4*)(g_qn + arow_off + lkc);
    float4 rb = *(const float4*)(wbase + (size_t)bkr * DD + bn4);
#pragma unroll
    for (int j = 0; j < 4; j++) As[0][lkc + j][lrow] = ((const float*)&ra)[j];
    *(float4*)&Bs[0][bkr][bn4] = rb;
    __syncthreads();

    for (int s = 0; s < 32; s++) {
        int buf = s & 1;
        if (s + 1 < 32) {
            int k0 = (s + 1) * 16;
            ra = *(const float4*)(g_qn + arow_off + k0 + lkc);
            rb = *(const float4*)(wbase + (size_t)(k0 + bkr) * DD + bn4);
        }
#pragma unroll
        for (int k = 0; k < 16; k++) {
            float ar[4], br[4];
            *(float4*)ar = *(const float4*)&As[buf][k][trow * 4];
            *(float4*)br = *(const float4*)&Bs[buf][k][tcol * 4];
#pragma unroll
            for (int i = 0; i < 4; i++)
#pragma unroll
                for (int j = 0; j < 4; j++) acc[i][j] += ar[i] * br[j];
        }
        if (s + 1 < 32) {
            __syncthreads();
#pragma unroll
            for (int j = 0; j < 4; j++) As[buf ^ 1][lkc + j][lrow] = ((const float*)&ra)[j];
            *(float4*)&Bs[buf ^ 1][bkr][bn4] = rb;
            __syncthreads();
        }
    }
#pragma unroll
    for (int i = 0; i < 4; i++) {
        float4 o;
        o.x = acc[i][0] * QK_SCALE; o.y = acc[i][1] * QK_SCALE;
        o.z = acc[i][2] * QK_SCALE; o.w = acc[i][3] * QK_SCALE;
        *(float4*)&g_qt[(size_t)grow(m0 + trow * 4 + i) * DD + d0 + tcol * 4] = o;
    }
}

// ---------------------------------------------------------------------------
// Triangular quadratic-form norm GEMM:
//   z = H @ U^T  (U upper-tri fp16, zero chunks skipped), sumsq = 2*sum(z .* h).
// Same pipeline/smem/ldmatrix mappings as the validated R13 kernel.
// grid 2048 = b(64) x n(4) x stile(4) x ehalf(2); ehalf0 -> etiles {0,3} (16+4
// chunks), ehalf1 -> {1,2} (12+8) -> both 20 chunks.  82KB smem, 2 CTA/SM.
// ---------------------------------------------------------------------------
#define KN_ROWB   80
#define KN_ATILE  (128 * KN_ROWB)            // 10240
#define KN_STAGE  (2 * KN_ATILE)             // 20480
#define KN_SMEM   (4 * KN_STAGE)             // 81920
#define KN_NCH    20

__global__ void __launch_bounds__(256) k_knorm_tri() {
    extern __shared__ __align__(16) char smem[];
    uint32_t sbase = smem_u32(smem);

    int tid = threadIdx.x;
    int wid = tid >> 5, lane = tid & 31;
    int warp_m = wid & 3;
    int warp_n = wid >> 2;

    int bx = blockIdx.x;
    int ehalf = bx & 1;
    int stile = (bx >> 1) & 3;
    int n = (bx >> 3) & 3;
    int b = bx >> 5;
    int s0 = stile * 128;

    const __half* Abase = g_hH + (size_t)b * SS * DD;
    const __half* Bm = g_bu + (size_t)n * DD * DD;

    int etA = (ehalf == 0) ? 0 : 1;
    int etB = (ehalf == 0) ? 3 : 2;
    int jf1 = (ehalf == 0) ? 15 : 11;

    int lrow = tid >> 1;
    int lhalf = tid & 1;
    size_t a_goff = (size_t)(s0 + lrow) * DD + lhalf * 16;
    uint32_t s_loff = (uint32_t)(lrow * KN_ROWB + lhalf * 32);

    int g = lane >> 3, lr = lane & 7;
    int a_row16 = ((g & 1) << 3) + lr;
    int a_kc = g >> 1;
    uint32_t a_off0 = (uint32_t)((warp_m * 32 + a_row16) * KN_ROWB + a_kc * 16);
    uint32_t a_off1 = a_off0 + 16 * KN_ROWB;
    int b_row16 = ((g >> 1) << 3) + lr;
    int b_kc = g & 1;
    uint32_t b_off[4];
#pragma unroll
    for (int p = 0; p < 4; p++)
        b_off[p] = (uint32_t)(KN_ATILE +
                   (warp_n * 64 + p * 16 + b_row16) * KN_ROWB + b_kc * 16);

    float acc[2][8][4];
#pragma unroll
    for (int mt = 0; mt < 2; mt++)
#pragma unroll
        for (int nt = 0; nt < 8; nt++)
#pragma unroll
            for (int c = 0; c < 4; c++) acc[mt][nt][c] = 0.0f;
    float rs[2][2] = {{0.f, 0.f}, {0.f, 0.f}};

    // chunk map: j -> (etile, kstage)
    auto chunk_map = [&](int j, int& et, int& ks) {
        if (ehalf == 0) { if (j < 16) { et = 0; ks = j; } else { et = 3; ks = j - 4; } }
        else            { if (j < 12) { et = 1; ks = j + 4; } else { et = 2; ks = j - 4; } }
    };

    auto load_stage = [&](int j) {
        int et, ks;
        chunk_map(j, et, ks);
        int k0 = ks * 32;
        uint32_t sb = sbase + (uint32_t)(j & 3) * KN_STAGE;
        const __half* as = Abase + a_goff + k0;
        const __half* bs = Bm + (size_t)(et * 128 + lrow) * DD + lhalf * 16 + k0;
        cp_async16(sb + s_loff, as);
        cp_async16(sb + s_loff + 16, as + 8);
        cp_async16(sb + KN_ATILE + s_loff, bs);
        cp_async16(sb + KN_ATILE + s_loff + 16, bs + 8);
        CPASYNC_COMMIT();
    };

    load_stage(0);
    load_stage(1);
    load_stage(2);

    for (int i = 0; i < KN_NCH; i++) {
        if (i < KN_NCH - 2)      { CPASYNC_WAIT2(); }
        else if (i == KN_NCH - 2){ CPASYNC_WAIT1(); }
        else                     { CPASYNC_WAIT0(); }
        __syncthreads();
        if (i + 3 < KN_NCH) load_stage(i + 3);

        uint32_t sb = sbase + (uint32_t)(i & 3) * KN_STAGE;
#pragma unroll
        for (int ks = 0; ks < 2; ks++) {
            uint32_t koff = (uint32_t)(ks * 32);
            uint32_t afrag[2][4];
            uint32_t bfrag[8][2];
            ldmatrix_x4(afrag[0][0], afrag[0][1], afrag[0][2], afrag[0][3],
                        sb + a_off0 + koff);
            ldmatrix_x4(afrag[1][0], afrag[1][1], afrag[1][2], afrag[1][3],
                        sb + a_off1 + koff);
#pragma unroll
            for (int p = 0; p < 4; p++) {
                ldmatrix_x4(bfrag[2 * p][0], bfrag[2 * p][1],
                            bfrag[2 * p + 1][0], bfrag[2 * p + 1][1],
                            sb + b_off[p] + koff);
            }
#pragma unroll
            for (int mt = 0; mt < 2; mt++)
#pragma unroll
                for (int nt = 0; nt < 8; nt++)
                    mma_fp16(acc[mt][nt], afrag[mt], bfrag[nt]);
        }

        if (i == jf1 || i == KN_NCH - 1) {   // etile done: fold z .* h, reset
            int et = (i == KN_NCH - 1) ? etB : etA;
#pragma unroll
            for (int mt = 0; mt < 2; mt++) {
#pragma unroll
                for (int nt = 0; nt < 8; nt++) {
                    int r0 = warp_m * 32 + mt * 16 + (lane >> 2);
                    int c = et * 128 + warp_n * 64 + nt * 8 + (lane & 3) * 2;
                    float2 fa = __half22float2(*(const __half2*)
                        &g_hH[((size_t)(b * SS + s0 + r0)) * DD + c]);
                    float2 fb = __half22float2(*(const __half2*)
                        &g_hH[((size_t)(b * SS + s0 + r0 + 8)) * DD + c]);
                    rs[mt][0] += acc[mt][nt][0] * fa.x + acc[mt][nt][1] * fa.y;
                    rs[mt][1] += acc[mt][nt][2] * fb.x + acc[mt][nt][3] * fb.y;
                    acc[mt][nt][0] = acc[mt][nt][1] = 0.f;
                    acc[mt][nt][2] = acc[mt][nt][3] = 0.f;
                }
            }
        }
    }

    // epilogue: quad-reduce, combine via smem, store 2*sum to ehalf buffer
#pragma unroll
    for (int mt = 0; mt < 2; mt++) {
#pragma unroll
        for (int h = 0; h < 2; h++) {
            rs[mt][h] += __shfl_xor_sync(0xFFFFFFFFu, rs[mt][h], 1);
            rs[mt][h] += __shfl_xor_sync(0xFFFFFFFFu, rs[mt][h], 2);
        }
    }
    __syncthreads();
    float* ssum = (float*)smem;
    if (tid < 128) ssum[tid] = 0.0f;
    __syncthreads();
    if ((lane & 3) == 0) {
        int rbase = warp_m * 32 + (lane >> 2);
#pragma unroll
        for (int mt = 0; mt < 2; mt++) {
            atomicAdd(&ssum[rbase + mt * 16], rs[mt][0]);
            atomicAdd(&ssum[rbase + mt * 16 + 8], rs[mt][1]);
        }
    }
    __syncthreads();
    if (tid < 128)
        g_sumsq2[ehalf][((size_t)(b * NKVH + n)) * SS + s0 + tid] = 2.0f * ssum[tid];
}

// ---------------------------------------------------------------------------
// Scores (smem-tiled): grid 256 = b(64) x stile(4), 256 thr.
// ---------------------------------------------------------------------------
__global__ void __launch_bounds__(256) k_scores(const float* __restrict__ hist,
                                                const void*  __restrict__ mask) {
    int b = blockIdx.x >> 2;
    int s0 = (blockIdx.x & 3) * 128;
    int tid = threadIdx.x;
    int mode = g_mask_mode;

    __shared__ float sqt[TT][516];
    __shared__ float sh[128][36];

    for (int i = tid; i < TT * DD; i += 256)
        sqt[i >> 9][i & 511] = g_qt[(size_t)(b * TT) * DD + i];

    int sl = tid >> 1;
    int pair = tid & 1;
    float acc[4] = {0.f, 0.f, 0.f, 0.f};

    for (int c = 0; c < 16; c++) {
        int d0 = c * 32;
        __syncthreads();
#pragma unroll
        for (int i = 0; i < 4; i++) {
            int idx = tid + i * 256;
            int r = idx >> 3, cc = idx & 7;
            float4 v = *(const float4*)(hist + ((size_t)(b * SS + s0 + r)) * DD
                                        + d0 + cc * 4);
            *(float4*)&sh[r][cc * 4] = v;
        }
        __syncthreads();
        const float4* hrow = (const float4*)sh[sl];
        const float4* q0 = (const float4*)&sqt[pair * 4 + 0][d0];
        const float4* q1 = (const float4*)&sqt[pair * 4 + 1][d0];
        const float4* q2 = (const float4*)&sqt[pair * 4 + 2][d0];
        const float4* q3 = (const float4*)&sqt[pair * 4 + 3][d0];
#pragma unroll
        for (int d4 = 0; d4 < 8; d4++) {
            float4 h = hrow[d4];
            float4 a0 = q0[d4];
            float4 a1 = q1[d4];
            float4 a2 = q2[d4];
            float4 a3 = q3[d4];
            acc[0] += h.x * a0.x + h.y * a0.y + h.z * a0.z + h.w * a0.w;
            acc[1] += h.x * a1.x + h.y * a1.y + h.z * a1.z + h.w * a1.w;
            acc[2] += h.x * a2.x + h.y * a2.y + h.z * a2.z + h.w * a2.w;
            acc[3] += h.x * a3.x + h.y * a3.y + h.z * a3.z + h.w * a3.w;
        }
    }

    int s = s0 + sl;
    bool mk = is_masked(mask, b * SS + s, mode);
#pragma unroll
    for (int i = 0; i < 4; i++) {
        int t = pair * 4 + i;
        int n = t >> 1;
        size_t qi = ((size_t)(b * NKVH + n)) * SS + s;
        float sq = g_sumsq2[0][qi] + g_sumsq2[1][qi];
        float inv = rsqrtf(sq * (1.0f / (float)DD) + EPS);
        g_sc[((size_t)(b * TT + t)) * SS + s] = mk ? -INFINITY : acc[i] * inv;
    }
}

// ---------------------------------------------------------------------------
// Softmax: grid 64 (b), 256 thr, warp per t row.
// ---------------------------------------------------------------------------
__global__ void __launch_bounds__(256) k_softmax(float* __restrict__ out) {
    int b = blockIdx.x;
    int t = threadIdx.x >> 5, lane = threadIdx.x & 31;
    float* row = g_sc + ((size_t)(b * TT + t)) * SS;
    float v[16];
    float mx = -INFINITY;
#pragma unroll
    for (int j = 0; j < 16; j++) {
        v[j] = row[lane + 32 * j];
        mx = fmaxf(mx, v[j]);
    }
#pragma unroll
    for (int off = 16; off > 0; off >>= 1)
        mx = fmaxf(mx, __shfl_xor_sync(0xFFFFFFFFu, mx, off));
    float sum = 0.0f;
#pragma unroll
    for (int j = 0; j < 16; j++) { v[j] = expf(v[j] - mx); sum += v[j]; }
#pragma unroll
    for (int off = 16; off > 0; off >>= 1)
        sum += __shfl_xor_sync(0xFFFFFFFFu, sum, off);
    float is = 1.0f / sum;
    size_t wbase = (size_t)BB * TT * DD + ((size_t)(b * TT + t)) * SS;
#pragma unroll
    for (int j = 0; j < 16; j++) {
        float a = v[j] * is;
        row[lane + 32 * j] = a;
        out[wbase + lane + 32 * j] = a;
    }
}

// ---------------------------------------------------------------------------
// ctx partials: grid 256 = b(64) x stile(4), 512 thr (thread = d).
// ---------------------------------------------------------------------------
__global__ void __launch_bounds__(512) k_ctx(const float* __restrict__ hist) {
    int b = blockIdx.x >> 2;
    int stile = blockIdx.x & 3;
    int s0 = stile * 128;
    int tid = threadIdx.x;

    __shared__ float sat[TT][128];
    for (int i = tid; i < TT * 128; i += 512)
        sat[i >> 7][i & 127] = g_sc[((size_t)(b * TT + (i >> 7))) * SS + s0 + (i & 127)];
    __syncthreads();

    int d = tid;
    float acc[TT];
#pragma unroll
    for (int t = 0; t < TT; t++) acc[t] = 0.0f;
    const float* hp = hist + ((size_t)(b * SS + s0)) * DD + d;
    for (int s = 0; s < 128; s += 4) {
        float h0 = hp[(size_t)s * DD];
        float h1 = hp[(size_t)(s + 1) * DD];
        float h2 = hp[(size_t)(s + 2) * DD];
        float h3 = hp[(size_t)(s + 3) * DD];
#pragma unroll
        for (int t = 0; t < TT; t++) {
            float4 a = *(const float4*)&sat[t][s];
            acc[t] += a.x * h0 + a.y * h1 + a.z * h2 + a.w * h3;
        }
    }
#pragma unroll
    for (int t = 0; t < TT; t++)
        g_ctxp[stile][((size_t)(b * TT + t)) * DD + d] = acc[t];
}

// ---------------------------------------------------------------------------
// Out projection: tokens[m,e] = (sum of 4 ctx partials)[m,:] . Wv_n[e,:]
// ---------------------------------------------------------------------------
__global__ void __launch_bounds__(256) k_out(const float* __restrict__ Wv,
                                             float* __restrict__ out) {
    __shared__ float As[2][16][132];
    __shared__ float Bs[2][16][36];
    int tid = threadIdx.x;
    int n  = blockIdx.x >> 4;
    int e0 = (blockIdx.x & 15) * 32;

    int trow = tid >> 3;
    int tcol = tid & 7;

    float acc[4][4];
#pragma unroll
    for (int i = 0; i < 4; i++)
#pragma unroll
        for (int j = 0; j < 4; j++) acc[i][j] = 0.0f;

    int arow0 = tid >> 2, akc = (tid & 3) * 4;
    int brow = tid >> 2, bkc = (tid & 3) * 4;
    auto ctxrow = [&](int m) { return (m >> 1) * TT + n * 2 + (m & 1); };

    auto loadA = [&](int row, int off) {
        float4 r = *(const float4*)(&g_ctxp[0][0] + (size_t)row * DD + off);
#pragma unroll
        for (int p = 1; p < 4; p++) {
            float4 q = *(const float4*)(&g_ctxp[p][0] + (size_t)row * DD + off);
            r.x += q.x; r.y += q.y; r.z += q.z; r.w += q.w;
        }
        return r;
    };
    auto gload = [&](int s, float4* ra, float4* rb) {
        int k0 = s * 16;
        ra[0] = loadA(ctxrow(arow0), k0 + akc);
        ra[1] = loadA(ctxrow(arow0 + 64), k0 + akc);
        if (tid < 128)
            rb[0] = *(const float4*)(Wv + (size_t)(n * DD + e0 + brow) * DD + k0 + bkc);
    };
    auto sstore = [&](int buf, const float4* ra, const float4* rb) {
#pragma unroll
        for (int j = 0; j < 4; j++) {
            As[buf][akc + j][arow0]      = ((const float*)&ra[0])[j];
            As[buf][akc + j][arow0 + 64] = ((const float*)&ra[1])[j];
        }
        if (tid < 128)
#pragma unroll
            for (int j = 0; j < 4; j++)
                Bs[buf][bkc + j][brow] = ((const float*)&rb[0])[j];
    };

    float4 ra[2], rb[1];
    gload(0, ra, rb);
    sstore(0, ra, rb);
    __syncthreads();

    for (int s = 0; s < 32; s++) {
        int buf = s & 1;
        if (s + 1 < 32) gload(s + 1, ra, rb);
#pragma unroll
        for (int k = 0; k < 16; k++) {
            float arr[4], brr[4];
            *(float4*)arr = *(const float4*)&As[buf][k][trow * 4];
            *(float4*)brr = *(const float4*)&Bs[buf][k][tcol * 4];
#pragma unroll
            for (int i = 0; i < 4; i++)
#pragma unroll
                for (int j = 0; j < 4; j++) acc[i][j] += arr[i] * brr[j];
        }
        if (s + 1 < 32) {
            __syncthreads();
            sstore(buf ^ 1, ra, rb);
            __syncthreads();
        }
    }
#pragma unroll
    for (int i = 0; i < 4; i++) {
        int m = trow * 4 + i;
        *(float4*)&out[(size_t)ctxrow(m) * DD + e0 + tcol * 4] = *(float4*)acc[i];
    }
}

// ---------------------------------------------------------------------------
extern "C" void kernel_launch(void* const* d_in, const int* in_sizes, int n_in,
                              void* d_out, int out_size) {
    (void)in_sizes; (void)n_in; (void)out_size;
    const float* target = (const float*)d_in[0];
    const float* hist   = (const float*)d_in[1];
    const void*  mask   = d_in[2];
    const float* Wq     = (const float*)d_in[3];
    const float* Wk     = (const float*)d_in[4];
    const float* Wv     = (const float*)d_in[5];
    const float* qw     = (const float*)d_in[6];
    const float* kw     = (const float*)d_in[7];
    float* out = (float*)d_out;

    static cudaStream_t sQ = nullptr;
    static cudaEvent_t evFork = nullptr, evG = nullptr, evJoin = nullptr;
    if (sQ == nullptr) {
        cudaStreamCreateWithFlags(&sQ, cudaStreamNonBlocking);
        cudaEventCreateWithFlags(&evFork, cudaEventDisableTiming);
        cudaEventCreateWithFlags(&evG, cudaEventDisableTiming);
        cudaEventCreateWithFlags(&evJoin, cudaEventDisableTiming);
        cudaFuncSetAttribute(k_knorm_tri,
                             cudaFuncAttributeMaxDynamicSharedMemorySize, KN_SMEM);
    }

    __half *hH, *wH;
    cudaGetSymbolAddress((void**)&hH, g_hH);
    cudaGetSymbolAddress((void**)&wH, g_wH);

    // fork: gram chain + q-chain + mask sniff on side stream
    cudaEventRecord(evFork, 0);
    cudaStreamWaitEvent(sQ, evFork, 0);
    k_tofp16<<<512, 256, 0, sQ>>>(Wk, wH, NKVH * DD * DD / 4);
    k_gram<<<64, 256, 0, sQ>>>();
    k_build_u<<<2048, 256, 0, sQ>>>();
    cudaEventRecord(evG, sQ);
    k_detect_mask<<<1, 256, 0, sQ>>>((const unsigned int*)mask);
    k_qproj_gemm<<<64, 256, 0, sQ>>>(target, Wq);
    k_qnorm<<<64, 256, 0, sQ>>>(qw, kw);
    k_qtilde_gemm<<<64, 256, 0, sQ>>>(Wk);
    cudaEventRecord(evJoin, sQ);

    // main chain
    k_tofp16<<<2048, 256>>>(hist, hH, BB * SS * DD / 4);
    cudaStreamWaitEvent(0, evG, 0);
    k_knorm_tri<<<BB * NKVH * 4 * 2, 256, KN_SMEM>>>();

    // join: scores needs g_qt + g_mask_mode (sQ) and g_sumsq2 (main)
    cudaStreamWaitEvent(0, evJoin, 0);
    k_scores<<<256, 256>>>(hist, mask);
    k_softmax<<<64, 256>>>(out);
    k_ctx<<<256, 512>>>(hist);
    k_out<<<64, 256>>>(Wv, out);
}

// round 15
// speedup vs baseline: 1.1933x; 1.1933x over previous
#include <cuda_runtime.h>
#include <cuda_fp16.h>
#include <math.h>
#include <stdint.h>

// Problem constants
#define BB   64
#define TT   8
#define DD   512
#define SS   512
#define NKVH 4
#define QK_SCALE 0.044194173824159216f
#define EPS 1e-6f

// ---------------------------------------------------------------------------
// Device-global scratch
// ---------------------------------------------------------------------------
__device__ float g_q[BB * TT * DD];          // raw q projection
__device__ float g_qn[BB * TT * DD];         // normalized q * (1+qw)(1+kw)
__device__ float g_qt[BB * TT * DD];         // q-tilde
__device__ float g_sumsq2[2][BB * NKVH * SS];// sumsq partials (etile-pair halves)
__device__ float g_sc[BB * TT * SS];         // scores, then attn
__device__ float g_ctxp[4][BB * TT * DD];    // ctx partials per stile
__device__ int   g_mask_mode;
__device__ __half g_hH[BB * SS * DD];        // hist fp16
__device__ __half g_bu[NKVH * DD * DD];      // U = triu(W^T W), half diag, fp16

// Gram tile-pair table: 64x64 tiles (t1,t2) with t2 >= (t1 & ~1)  (40 pairs)
__device__ const signed char GP_T1[40] = {
    0,0,0,0,0,0,0,0, 1,1,1,1,1,1,1,1, 2,2,2,2,2,2, 3,3,3,3,3,3,
    4,4,4,4, 5,5,5,5, 6,6, 7,7 };
__device__ const signed char GP_T2[40] = {
    0,1,2,3,4,5,6,7, 0,1,2,3,4,5,6,7, 2,3,4,5,6,7, 2,3,4,5,6,7,
    4,5,6,7, 4,5,6,7, 6,7, 6,7 };

// ---------------------------------------------------------------------------
// PTX helpers
// ---------------------------------------------------------------------------
__device__ __forceinline__ uint32_t smem_u32(const void* p) {
    uint32_t a;
    asm("{ .reg .u64 t; cvta.to.shared.u64 t, %1; cvt.u32.u64 %0, t; }"
        : "=r"(a) : "l"(p));
    return a;
}
__device__ __forceinline__ void cp_async16(uint32_t dst, const void* src) {
    asm volatile("cp.async.cg.shared.global [%0], [%1], 16;"
                 :: "r"(dst), "l"(src));
}
#define CPASYNC_COMMIT() asm volatile("cp.async.commit_group;" ::: "memory")
#define CPASYNC_WAIT2()  asm volatile("cp.async.wait_group 2;" ::: "memory")
#define CPASYNC_WAIT1()  asm volatile("cp.async.wait_group 1;" ::: "memory")
#define CPASYNC_WAIT0()  asm volatile("cp.async.wait_group 0;" ::: "memory")

__device__ __forceinline__ void ldmatrix_x4(uint32_t& r0, uint32_t& r1,
                                            uint32_t& r2, uint32_t& r3,
                                            uint32_t addr) {
    asm volatile("ldmatrix.sync.aligned.m8n8.x4.shared.b16 {%0,%1,%2,%3}, [%4];"
                 : "=r"(r0), "=r"(r1), "=r"(r2), "=r"(r3) : "r"(addr));
}
__device__ __forceinline__ void mma_fp16(float* d, const uint32_t* a,
                                         const uint32_t* b) {
    asm volatile(
        "mma.sync.aligned.m16n8k16.row.col.f32.f16.f16.f32 "
        "{%0,%1,%2,%3}, {%4,%5,%6,%7}, {%8,%9}, {%0,%1,%2,%3};"
        : "+f"(d[0]), "+f"(d[1]), "+f"(d[2]), "+f"(d[3])
        : "r"(a[0]), "r"(a[1]), "r"(a[2]), "r"(a[3]), "r"(b[0]), "r"(b[1]));
}

// ---------------------------------------------------------------------------
// Mask dtype sniffer
// ---------------------------------------------------------------------------
__global__ void k_detect_mask(const unsigned int* __restrict__ m) {
    __shared__ int flags[3];
    int tid = threadIdx.x;
    if (tid < 3) flags[tid] = 1;
    __syncthreads();
    int iok = 1, fok = 1, hok = 1;
    for (int i = tid; i < 8192; i += blockDim.x) {
        unsigned w = m[i];
        if (w > 1u) iok = 0;
        float f = __uint_as_float(w);
        if (!(f == 0.0f || f == 1.0f)) fok = 0;
        unsigned lo = w & 0xFFFFu, hi = w >> 16;
        if (!((lo == 0u || lo == 0x3F80u) && (hi == 0u || hi == 0x3F80u))) hok = 0;
    }
    if (!iok) atomicExch(&flags[0], 0);
    if (!fok) atomicExch(&flags[1], 0);
    if (!hok) atomicExch(&flags[2], 0);
    __syncthreads();
    if (tid == 0)
        g_mask_mode = flags[0] ? 0 : (flags[1] ? 1 : (flags[2] ? 3 : 2));
}
__device__ __forceinline__ bool is_masked(const void* m, int idx, int mode) {
    if (mode == 0) return ((const int*)m)[idx] != 0;
    if (mode == 1) return ((const float*)m)[idx] != 0.0f;
    if (mode == 3) return ((const unsigned short*)m)[idx] != 0;
    return ((const unsigned char*)m)[idx] != 0;
}

// ---------------------------------------------------------------------------
// fp32 -> fp16 conversion
// ---------------------------------------------------------------------------
__global__ void k_tofp16(const float* __restrict__ src,
                         __half* __restrict__ dst, int n4) {
    int i = blockIdx.x * blockDim.x + threadIdx.x;
    int stride = gridDim.x * blockDim.x;
    for (; i < n4; i += stride) {
        float4 v = ((const float4*)src)[i];
        ((__half2*)dst)[i * 2 + 0] = __floats2half2_rn(v.x, v.y);
        ((__half2*)dst)[i * 2 + 1] = __floats2half2_rn(v.z, v.w);
    }
}

// ---------------------------------------------------------------------------
// Gram (SIMT fp32, no transpose): U[d1][d2] = triu/half-diag of
//   sum_e W[e,d1]*W[e,d2], written as fp16 into g_bu.
// grid 160 = n(4) x pair(40); 64x64 tile, K=512 in 16-row stages, double buf.
// Operand staging is direct-copy (W is [e][d], e = K): conflict-free.
// ---------------------------------------------------------------------------
__global__ void __launch_bounds__(256) k_gram_simt(const float* __restrict__ Wk) {
    __shared__ float As[2][16][68];
    __shared__ float Bs[2][16][68];
    int tid = threadIdx.x;
    int pair = blockIdx.x % 40;
    int n = blockIdx.x / 40;
    int t1 = GP_T1[pair];
    int t2 = GP_T2[pair];
    int d1o = t1 * 64;
    int d2o = t2 * 64;

    const float* W = Wk + (size_t)n * DD * DD;

    int ler = tid >> 4;            // 0..15 (k row)
    int ldc = (tid & 15) * 4;      // 0..60 (col)
    int trow = tid >> 4;
    int tcol = tid & 15;

    float acc[4][4];
#pragma unroll
    for (int i = 0; i < 4; i++)
#pragma unroll
        for (int j = 0; j < 4; j++) acc[i][j] = 0.0f;

    float4 ra = *(const float4*)(W + (size_t)ler * DD + d1o + ldc);
    float4 rb = *(const float4*)(W + (size_t)ler * DD + d2o + ldc);
    *(float4*)&As[0][ler][ldc] = ra;
    *(float4*)&Bs[0][ler][ldc] = rb;
    __syncthreads();

    for (int s = 0; s < 32; s++) {
        int buf = s & 1;
        if (s + 1 < 32) {
            int e0 = (s + 1) * 16;
            ra = *(const float4*)(W + (size_t)(e0 + ler) * DD + d1o + ldc);
            rb = *(const float4*)(W + (size_t)(e0 + ler) * DD + d2o + ldc);
        }
#pragma unroll
        for (int k = 0; k < 16; k++) {
            float ar[4], br[4];
            *(float4*)ar = *(const float4*)&As[buf][k][trow * 4];
            *(float4*)br = *(const float4*)&Bs[buf][k][tcol * 4];
#pragma unroll
            for (int i = 0; i < 4; i++)
#pragma unroll
                for (int j = 0; j < 4; j++) acc[i][j] += ar[i] * br[j];
        }
        if (s + 1 < 32) {
            __syncthreads();
            *(float4*)&As[buf ^ 1][ler][ldc] = ra;
            *(float4*)&Bs[buf ^ 1][ler][ldc] = rb;
            __syncthreads();
        }
    }

    __half* U = g_bu + (size_t)n * DD * DD;
#pragma unroll
    for (int i = 0; i < 4; i++) {
        int d1 = d1o + trow * 4 + i;
        float u[4];
#pragma unroll
        for (int j = 0; j < 4; j++) {
            int d2 = d2o + tcol * 4 + j;
            float gg = acc[i][j];
            u[j] = (d2 > d1) ? gg : ((d2 == d1) ? 0.5f * gg : 0.0f);
        }
        __half2 h0 = __floats2half2_rn(u[0], u[1]);
        __half2 h1 = __floats2half2_rn(u[2], u[3]);
        *(__half2*)&U[(size_t)d1 * DD + d2o + tcol * 4] = h0;
        *(__half2*)&U[(size_t)d1 * DD + d2o + tcol * 4 + 2] = h1;
    }
}

// ---------------------------------------------------------------------------
// Raw Q projection: coalesced tiled SGEMM, 64x64 tiles, double-buffered.
// ---------------------------------------------------------------------------
__global__ void __launch_bounds__(256) k_qproj_gemm(const float* __restrict__ tgt,
                                                    const float* __restrict__ Wq) {
    __shared__ float As[2][16][68];
    __shared__ float Bs[2][16][68];
    int tid = threadIdx.x;
    int m0 = (blockIdx.x >> 3) * 64;
    int e0 = (blockIdx.x & 7) * 64;

    int lrow = tid >> 2;
    int lkc  = (tid & 3) * 4;
    int trow = tid >> 4;
    int tcol = tid & 15;

    float acc[4][4];
#pragma unroll
    for (int i = 0; i < 4; i++)
#pragma unroll
        for (int j = 0; j < 4; j++) acc[i][j] = 0.0f;

    float4 ra = *(const float4*)(tgt + (size_t)(m0 + lrow) * DD + lkc);
    float4 rb = *(const float4*)(Wq  + (size_t)(e0 + lrow) * DD + lkc);
#pragma unroll
    for (int j = 0; j < 4; j++) {
        As[0][lkc + j][lrow] = ((const float*)&ra)[j];
        Bs[0][lkc + j][lrow] = ((const float*)&rb)[j];
    }
    __syncthreads();

    for (int s = 0; s < 32; s++) {
        int buf = s & 1;
        if (s + 1 < 32) {
            int k0 = (s + 1) * 16;
            ra = *(const float4*)(tgt + (size_t)(m0 + lrow) * DD + k0 + lkc);
            rb = *(const float4*)(Wq  + (size_t)(e0 + lrow) * DD + k0 + lkc);
        }
#pragma unroll
        for (int k = 0; k < 16; k++) {
            float ar[4], br[4];
            *(float4*)ar = *(const float4*)&As[buf][k][trow * 4];
            *(float4*)br = *(const float4*)&Bs[buf][k][tcol * 4];
#pragma unroll
            for (int i = 0; i < 4; i++)
#pragma unroll
                for (int j = 0; j < 4; j++) acc[i][j] += ar[i] * br[j];
        }
        if (s + 1 < 32) {
            __syncthreads();
#pragma unroll
            for (int j = 0; j < 4; j++) {
                As[buf ^ 1][lkc + j][lrow] = ((const float*)&ra)[j];
                Bs[buf ^ 1][lkc + j][lrow] = ((const float*)&rb)[j];
            }
            __syncthreads();
        }
    }
#pragma unroll
    for (int i = 0; i < 4; i++)
        *(float4*)&g_q[(size_t)(m0 + trow * 4 + i) * DD + e0 + tcol * 4] =
            *(float4*)acc[i];
}

// ---------------------------------------------------------------------------
// Q RMS-norm: one warp per row; qn = q*inv_rms*(1+qw)*(1+kw)
// ---------------------------------------------------------------------------
__global__ void __launch_bounds__(256) k_qnorm(const float* __restrict__ qw,
                                               const float* __restrict__ kw) {
    int wid = threadIdx.x >> 5, lane = threadIdx.x & 31;
    int row = blockIdx.x * 8 + wid;
    const float4* src = (const float4*)(g_q + (size_t)row * DD);
    float4 v[4];
    float ss = 0.0f;
#pragma unroll
    for (int j = 0; j < 4; j++) {
        v[j] = src[lane + 32 * j];
        ss += v[j].x * v[j].x + v[j].y * v[j].y + v[j].z * v[j].z + v[j].w * v[j].w;
    }
#pragma unroll
    for (int off = 16; off > 0; off >>= 1)
        ss += __shfl_xor_sync(0xFFFFFFFFu, ss, off);
    float inv = rsqrtf(ss * (1.0f / (float)DD) + EPS);
    float4* dst = (float4*)(g_qn + (size_t)row * DD);
#pragma unroll
    for (int j = 0; j < 4; j++) {
        int e4 = (lane + 32 * j) * 4;
        float4 wq = *(const float4*)(qw + e4);
        float4 wk = *(const float4*)(kw + e4);
        float4 o;
        o.x = v[j].x * inv * (1.0f + wq.x) * (1.0f + wk.x);
        o.y = v[j].y * inv * (1.0f + wq.y) * (1.0f + wk.y);
        o.z = v[j].z * inv * (1.0f + wq.z) * (1.0f + wk.z);
        o.w = v[j].w * inv * (1.0f + wq.w) * (1.0f + wk.w);
        dst[lane + 32 * j] = o;
    }
}

// ---------------------------------------------------------------------------
// q-tilde GEMM: qt[m,d] = sum_e qn[m,e] * Wk[n*D+e, d] * SCALE
// ---------------------------------------------------------------------------
__global__ void __launch_bounds__(256) k_qtilde_gemm(const float* __restrict__ Wk) {
    __shared__ float As[2][16][68];
    __shared__ float Bs[2][16][68];
    int tid = threadIdx.x;
    int n  = blockIdx.x >> 4;
    int mt = (blockIdx.x >> 3) & 1;
    int nt = blockIdx.x & 7;
    int m0 = mt * 64;
    int d0 = nt * 64;

    auto grow = [&](int m) { return (m >> 1) * TT + n * 2 + (m & 1); };

    int lrow = tid >> 2;
    int lkc  = (tid & 3) * 4;
    int bkr  = tid >> 4;
    int bn4  = (tid & 15) * 4;
    int trow = tid >> 4;
    int tcol = tid & 15;

    size_t arow_off = (size_t)grow(m0 + lrow) * DD;
    const float* wbase = Wk + (size_t)n * DD * DD + d0;

    float acc[4][4];
#pragma unroll
    for (int i = 0; i < 4; i++)
#pragma unroll
        for (int j = 0; j < 4; j++) acc[i][j] = 0.0f;

    float4 ra = *(const float4*)(g_qn + arow_off + lkc);
    float4 rb = *(const float4*)(wbase + (size_t)bkr * DD + bn4);
#pragma unroll
    for (int j = 0; j < 4; j++) As[0][lkc + j][lrow] = ((const float*)&ra)[j];
    *(float4*)&Bs[0][bkr][bn4] = rb;
    __syncthreads();

    for (int s = 0; s < 32; s++) {
        int buf = s & 1;
        if (s + 1 < 32) {
            int k0 = (s + 1) * 16;
            ra = *(const float4*)(g_qn + arow_off + k0 + lkc);
            rb = *(const float4*)(wbase + (size_t)(k0 + bkr) * DD + bn4);
        }
#pragma unroll
        for (int k = 0; k < 16; k++) {
            float ar[4], br[4];
            *(float4*)ar = *(const float4*)&As[buf][k][trow * 4];
            *(float4*)br = *(const float4*)&Bs[buf][k][tcol * 4];
#pragma unroll
            for (int i = 0; i < 4; i++)
#pragma unroll
                for (int j = 0; j < 4; j++) acc[i][j] += ar[i] * br[j];
        }
        if (s + 1 < 32) {
            __syncthreads();
#pragma unroll
            for (int j = 0; j < 4; j++) As[buf ^ 1][lkc + j][lrow] = ((const float*)&ra)[j];
            *(float4*)&Bs[buf ^ 1][bkr][bn4] = rb;
            __syncthreads();
        }
    }
#pragma unroll
    for (int i = 0; i < 4; i++) {
        float4 o;
        o.x = acc[i][0] * QK_SCALE; o.y = acc[i][1] * QK_SCALE;
        o.z = acc[i][2] * QK_SCALE; o.w = acc[i][3] * QK_SCALE;
        *(float4*)&g_qt[(size_t)grow(m0 + trow * 4 + i) * DD + d0 + tcol * 4] = o;
    }
}

// ---------------------------------------------------------------------------
// Triangular quadratic-form norm GEMM (validated R14):
//   z = H @ U^T, zero K-chunks skipped; sumsq = 2*sum(z .* h).
// grid 2048 = b(64) x n(4) x stile(4) x ehalf(2); both halves do 20 chunks.
// ---------------------------------------------------------------------------
#define KN_ROWB   80
#define KN_ATILE  (128 * KN_ROWB)            // 10240
#define KN_STAGE  (2 * KN_ATILE)             // 20480
#define KN_SMEM   (4 * KN_STAGE)             // 81920
#define KN_NCH    20

__global__ void __launch_bounds__(256) k_knorm_tri() {
    extern __shared__ __align__(16) char smem[];
    uint32_t sbase = smem_u32(smem);

    int tid = threadIdx.x;
    int wid = tid >> 5, lane = tid & 31;
    int warp_m = wid & 3;
    int warp_n = wid >> 2;

    int bx = blockIdx.x;
    int ehalf = bx & 1;
    int stile = (bx >> 1) & 3;
    int n = (bx >> 3) & 3;
    int b = bx >> 5;
    int s0 = stile * 128;

    const __half* Abase = g_hH + (size_t)b * SS * DD;
    const __half* Bm = g_bu + (size_t)n * DD * DD;

    int etA = (ehalf == 0) ? 0 : 1;
    int etB = (ehalf == 0) ? 3 : 2;
    int jf1 = (ehalf == 0) ? 15 : 11;

    int lrow = tid >> 1;
    int lhalf = tid & 1;
    size_t a_goff = (size_t)(s0 + lrow) * DD + lhalf * 16;
    uint32_t s_loff = (uint32_t)(lrow * KN_ROWB + lhalf * 32);

    int g = lane >> 3, lr = lane & 7;
    int a_row16 = ((g & 1) << 3) + lr;
    int a_kc = g >> 1;
    uint32_t a_off0 = (uint32_t)((warp_m * 32 + a_row16) * KN_ROWB + a_kc * 16);
    uint32_t a_off1 = a_off0 + 16 * KN_ROWB;
    int b_row16 = ((g >> 1) << 3) + lr;
    int b_kc = g & 1;
    uint32_t b_off[4];
#pragma unroll
    for (int p = 0; p < 4; p++)
        b_off[p] = (uint32_t)(KN_ATILE +
                   (warp_n * 64 + p * 16 + b_row16) * KN_ROWB + b_kc * 16);

    float acc[2][8][4];
#pragma unroll
    for (int mt = 0; mt < 2; mt++)
#pragma unroll
        for (int nt = 0; nt < 8; nt++)
#pragma unroll
            for (int c = 0; c < 4; c++) acc[mt][nt][c] = 0.0f;
    float rs[2][2] = {{0.f, 0.f}, {0.f, 0.f}};

    auto chunk_map = [&](int j, int& et, int& ks) {
        if (ehalf == 0) { if (j < 16) { et = 0; ks = j; } else { et = 3; ks = j - 4; } }
        else            { if (j < 12) { et = 1; ks = j + 4; } else { et = 2; ks = j - 4; } }
    };

    auto load_stage = [&](int j) {
        int et, ks;
        chunk_map(j, et, ks);
        int k0 = ks * 32;
        uint32_t sb = sbase + (uint32_t)(j & 3) * KN_STAGE;
        const __half* as = Abase + a_goff + k0;
        const __half* bs = Bm + (size_t)(et * 128 + lrow) * DD + lhalf * 16 + k0;
        cp_async16(sb + s_loff, as);
        cp_async16(sb + s_loff + 16, as + 8);
        cp_async16(sb + KN_ATILE + s_loff, bs);
        cp_async16(sb + KN_ATILE + s_loff + 16, bs + 8);
        CPASYNC_COMMIT();
    };

    load_stage(0);
    load_stage(1);
    load_stage(2);

    for (int i = 0; i < KN_NCH; i++) {
        if (i < KN_NCH - 2)      { CPASYNC_WAIT2(); }
        else if (i == KN_NCH - 2){ CPASYNC_WAIT1(); }
        else                     { CPASYNC_WAIT0(); }
        __syncthreads();
        if (i + 3 < KN_NCH) load_stage(i + 3);

        uint32_t sb = sbase + (uint32_t)(i & 3) * KN_STAGE;
#pragma unroll
        for (int ks = 0; ks < 2; ks++) {
            uint32_t koff = (uint32_t)(ks * 32);
            uint32_t afrag[2][4];
            uint32_t bfrag[8][2];
            ldmatrix_x4(afrag[0][0], afrag[0][1], afrag[0][2], afrag[0][3],
                        sb + a_off0 + koff);
            ldmatrix_x4(afrag[1][0], afrag[1][1], afrag[1][2], afrag[1][3],
                        sb + a_off1 + koff);
#pragma unroll
            for (int p = 0; p < 4; p++) {
                ldmatrix_x4(bfrag[2 * p][0], bfrag[2 * p][1],
                            bfrag[2 * p + 1][0], bfrag[2 * p + 1][1],
                            sb + b_off[p] + koff);
            }
#pragma unroll
            for (int mt = 0; mt < 2; mt++)
#pragma unroll
                for (int nt = 0; nt < 8; nt++)
                    mma_fp16(acc[mt][nt], afrag[mt], bfrag[nt]);
        }

        if (i == jf1 || i == KN_NCH - 1) {   // etile done: fold z .* h, reset
            int et = (i == KN_NCH - 1) ? etB : etA;
#pragma unroll
            for (int mt = 0; mt < 2; mt++) {
#pragma unroll
                for (int nt = 0; nt < 8; nt++) {
                    int r0 = warp_m * 32 + mt * 16 + (lane >> 2);
                    int c = et * 128 + warp_n * 64 + nt * 8 + (lane & 3) * 2;
                    float2 fa = __half22float2(*(const __half2*)
                        &g_hH[((size_t)(b * SS + s0 + r0)) * DD + c]);
                    float2 fb = __half22float2(*(const __half2*)
                        &g_hH[((size_t)(b * SS + s0 + r0 + 8)) * DD + c]);
                    rs[mt][0] += acc[mt][nt][0] * fa.x + acc[mt][nt][1] * fa.y;
                    rs[mt][1] += acc[mt][nt][2] * fb.x + acc[mt][nt][3] * fb.y;
                    acc[mt][nt][0] = acc[mt][nt][1] = 0.f;
                    acc[mt][nt][2] = acc[mt][nt][3] = 0.f;
                }
            }
        }
    }

    // epilogue: quad-reduce, combine via smem, store 2*sum to ehalf buffer
#pragma unroll
    for (int mt = 0; mt < 2; mt++) {
#pragma unroll
        for (int h = 0; h < 2; h++) {
            rs[mt][h] += __shfl_xor_sync(0xFFFFFFFFu, rs[mt][h], 1);
            rs[mt][h] += __shfl_xor_sync(0xFFFFFFFFu, rs[mt][h], 2);
        }
    }
    __syncthreads();
    float* ssum = (float*)smem;
    if (tid < 128) ssum[tid] = 0.0f;
    __syncthreads();
    if ((lane & 3) == 0) {
        int rbase = warp_m * 32 + (lane >> 2);
#pragma unroll
        for (int mt = 0; mt < 2; mt++) {
            atomicAdd(&ssum[rbase + mt * 16], rs[mt][0]);
            atomicAdd(&ssum[rbase + mt * 16 + 8], rs[mt][1]);
        }
    }
    __syncthreads();
    if (tid < 128)
        g_sumsq2[ehalf][((size_t)(b * NKVH + n)) * SS + s0 + tid] = 2.0f * ssum[tid];
}

// ---------------------------------------------------------------------------
// Scores (smem-tiled): grid 256 = b(64) x stile(4), 256 thr.
// ---------------------------------------------------------------------------
__global__ void __launch_bounds__(256) k_scores(const float* __restrict__ hist,
                                                const void*  __restrict__ mask) {
    int b = blockIdx.x >> 2;
    int s0 = (blockIdx.x & 3) * 128;
    int tid = threadIdx.x;
    int mode = g_mask_mode;

    __shared__ float sqt[TT][516];
    __shared__ float sh[128][36];

    for (int i = tid; i < TT * DD; i += 256)
        sqt[i >> 9][i & 511] = g_qt[(size_t)(b * TT) * DD + i];

    int sl = tid >> 1;
    int pair = tid & 1;
    float acc[4] = {0.f, 0.f, 0.f, 0.f};

    for (int c = 0; c < 16; c++) {
        int d0 = c * 32;
        __syncthreads();
#pragma unroll
        for (int i = 0; i < 4; i++) {
            int idx = tid + i * 256;
            int r = idx >> 3, cc = idx & 7;
            float4 v = *(const float4*)(hist + ((size_t)(b * SS + s0 + r)) * DD
                                        + d0 + cc * 4);
            *(float4*)&sh[r][cc * 4] = v;
        }
        __syncthreads();
        const float4* hrow = (const float4*)sh[sl];
        const float4* q0 = (const float4*)&sqt[pair * 4 + 0][d0];
        const float4* q1 = (const float4*)&sqt[pair * 4 + 1][d0];
        const float4* q2 = (const float4*)&sqt[pair * 4 + 2][d0];
        const float4* q3 = (const float4*)&sqt[pair * 4 + 3][d0];
#pragma unroll
        for (int d4 = 0; d4 < 8; d4++) {
            float4 h = hrow[d4];
            float4 a0 = q0[d4];
            float4 a1 = q1[d4];
            float4 a2 = q2[d4];
            float4 a3 = q3[d4];
            acc[0] += h.x * a0.x + h.y * a0.y + h.z * a0.z + h.w * a0.w;
            acc[1] += h.x * a1.x + h.y * a1.y + h.z * a1.z + h.w * a1.w;
            acc[2] += h.x * a2.x + h.y * a2.y + h.z * a2.z + h.w * a2.w;
            acc[3] += h.x * a3.x + h.y * a3.y + h.z * a3.z + h.w * a3.w;
        }
    }

    int s = s0 + sl;
    bool mk = is_masked(mask, b * SS + s, mode);
#pragma unroll
    for (int i = 0; i < 4; i++) {
        int t = pair * 4 + i;
        int n = t >> 1;
        size_t qi = ((size_t)(b * NKVH + n)) * SS + s;
        float sq = g_sumsq2[0][qi] + g_sumsq2[1][qi];
        float inv = rsqrtf(sq * (1.0f / (float)DD) + EPS);
        g_sc[((size_t)(b * TT + t)) * SS + s] = mk ? -INFINITY : acc[i] * inv;
    }
}

// ---------------------------------------------------------------------------
// Softmax: grid 64 (b), 256 thr, warp per t row.
// ---------------------------------------------------------------------------
__global__ void __launch_bounds__(256) k_softmax(float* __restrict__ out) {
    int b = blockIdx.x;
    int t = threadIdx.x >> 5, lane = threadIdx.x & 31;
    float* row = g_sc + ((size_t)(b * TT + t)) * SS;
    float v[16];
    float mx = -INFINITY;
#pragma unroll
    for (int j = 0; j < 16; j++) {
        v[j] = row[lane + 32 * j];
        mx = fmaxf(mx, v[j]);
    }
#pragma unroll
    for (int off = 16; off > 0; off >>= 1)
        mx = fmaxf(mx, __shfl_xor_sync(0xFFFFFFFFu, mx, off));
    float sum = 0.0f;
#pragma unroll
    for (int j = 0; j < 16; j++) { v[j] = expf(v[j] - mx); sum += v[j]; }
#pragma unroll
    for (int off = 16; off > 0; off >>= 1)
        sum += __shfl_xor_sync(0xFFFFFFFFu, sum, off);
    float is = 1.0f / sum;
    size_t wbase = (size_t)BB * TT * DD + ((size_t)(b * TT + t)) * SS;
#pragma unroll
    for (int j = 0; j < 16; j++) {
        float a = v[j] * is;
        row[lane + 32 * j] = a;
        out[wbase + lane + 32 * j] = a;
    }
}

// ---------------------------------------------------------------------------
// ctx partials: grid 256 = b(64) x stile(4), 512 thr (thread = d).
// ---------------------------------------------------------------------------
__global__ void __launch_bounds__(512) k_ctx(const float* __restrict__ hist) {
    int b = blockIdx.x >> 2;
    int stile = blockIdx.x & 3;
    int s0 = stile * 128;
    int tid = threadIdx.x;

    __shared__ float sat[TT][128];
    for (int i = tid; i < TT * 128; i += 512)
        sat[i >> 7][i & 127] = g_sc[((size_t)(b * TT + (i >> 7))) * SS + s0 + (i & 127)];
    __syncthreads();

    int d = tid;
    float acc[TT];
#pragma unroll
    for (int t = 0; t < TT; t++) acc[t] = 0.0f;
    const float* hp = hist + ((size_t)(b * SS + s0)) * DD + d;
    for (int s = 0; s < 128; s += 4) {
        float h0 = hp[(size_t)s * DD];
        float h1 = hp[(size_t)(s + 1) * DD];
        float h2 = hp[(size_t)(s + 2) * DD];
        float h3 = hp[(size_t)(s + 3) * DD];
#pragma unroll
        for (int t = 0; t < TT; t++) {
            float4 a = *(const float4*)&sat[t][s];
            acc[t] += a.x * h0 + a.y * h1 + a.z * h2 + a.w * h3;
        }
    }
#pragma unroll
    for (int t = 0; t < TT; t++)
        g_ctxp[stile][((size_t)(b * TT + t)) * DD + d] = acc[t];
}

// ---------------------------------------------------------------------------
// Out projection: tokens[m,e] = (sum of 4 ctx partials)[m,:] . Wv_n[e,:]
// ---------------------------------------------------------------------------
__global__ void __launch_bounds__(256) k_out(const float* __restrict__ Wv,
                                             float* __restrict__ out) {
    __shared__ float As[2][16][132];
    __shared__ float Bs[2][16][36];
    int tid = threadIdx.x;
    int n  = blockIdx.x >> 4;
    int e0 = (blockIdx.x & 15) * 32;

    int trow = tid >> 3;
    int tcol = tid & 7;

    float acc[4][4];
#pragma unroll
    for (int i = 0; i < 4; i++)
#pragma unroll
        for (int j = 0; j < 4; j++) acc[i][j] = 0.0f;

    int arow0 = tid >> 2, akc = (tid & 3) * 4;
    int brow = tid >> 2, bkc = (tid & 3) * 4;
    auto ctxrow = [&](int m) { return (m >> 1) * TT + n * 2 + (m & 1); };

    auto loadA = [&](int row, int off) {
        float4 r = *(const float4*)(&g_ctxp[0][0] + (size_t)row * DD + off);
#pragma unroll
        for (int p = 1; p < 4; p++) {
            float4 q = *(const float4*)(&g_ctxp[p][0] + (size_t)row * DD + off);
            r.x += q.x; r.y += q.y; r.z += q.z; r.w += q.w;
        }
        return r;
    };
    auto gload = [&](int s, float4* ra, float4* rb) {
        int k0 = s * 16;
        ra[0] = loadA(ctxrow(arow0), k0 + akc);
        ra[1] = loadA(ctxrow(arow0 + 64), k0 + akc);
        if (tid < 128)
            rb[0] = *(const float4*)(Wv + (size_t)(n * DD + e0 + brow) * DD + k0 + bkc);
    };
    auto sstore = [&](int buf, const float4* ra, const float4* rb) {
#pragma unroll
        for (int j = 0; j < 4; j++) {
            As[buf][akc + j][arow0]      = ((const float*)&ra[0])[j];
            As[buf][akc + j][arow0 + 64] = ((const float*)&ra[1])[j];
        }
        if (tid < 128)
#pragma unroll
            for (int j = 0; j < 4; j++)
                Bs[buf][bkc + j][brow] = ((const float*)&rb[0])[j];
    };

    float4 ra[2], rb[1];
    gload(0, ra, rb);
    sstore(0, ra, rb);
    __syncthreads();

    for (int s = 0; s < 32; s++) {
        int buf = s & 1;
        if (s + 1 < 32) gload(s + 1, ra, rb);
#pragma unroll
        for (int k = 0; k < 16; k++) {
            float arr[4], brr[4];
            *(float4*)arr = *(const float4*)&As[buf][k][trow * 4];
            *(float4*)brr = *(const float4*)&Bs[buf][k][tcol * 4];
#pragma unroll
            for (int i = 0; i < 4; i++)
#pragma unroll
                for (int j = 0; j < 4; j++) acc[i][j] += arr[i] * brr[j];
        }
        if (s + 1 < 32) {
            __syncthreads();
            sstore(buf ^ 1, ra, rb);
            __syncthreads();
        }
    }
#pragma unroll
    for (int i = 0; i < 4; i++) {
        int m = trow * 4 + i;
        *(float4*)&out[(size_t)ctxrow(m) * DD + e0 + tcol * 4] = *(float4*)acc[i];
    }
}

// ---------------------------------------------------------------------------
extern "C" void kernel_launch(void* const* d_in, const int* in_sizes, int n_in,
                              void* d_out, int out_size) {
    (void)in_sizes; (void)n_in; (void)out_size;
    const float* target = (const float*)d_in[0];
    const float* hist   = (const float*)d_in[1];
    const void*  mask   = d_in[2];
    const float* Wq     = (const float*)d_in[3];
    const float* Wk     = (const float*)d_in[4];
    const float* Wv     = (const float*)d_in[5];
    const float* qw     = (const float*)d_in[6];
    const float* kw     = (const float*)d_in[7];
    float* out = (float*)d_out;

    static cudaStream_t sQ = nullptr;
    static cudaEvent_t evFork = nullptr, evG = nullptr, evJoin = nullptr;
    if (sQ == nullptr) {
        cudaStreamCreateWithFlags(&sQ, cudaStreamNonBlocking);
        cudaEventCreateWithFlags(&evFork, cudaEventDisableTiming);
        cudaEventCreateWithFlags(&evG, cudaEventDisableTiming);
        cudaEventCreateWithFlags(&evJoin, cudaEventDisableTiming);
        cudaFuncSetAttribute(k_knorm_tri,
                             cudaFuncAttributeMaxDynamicSharedMemorySize, KN_SMEM);
    }

    __half* hH;
    cudaGetSymbolAddress((void**)&hH, g_hH);

    // fork: gram (SIMT, fp32 W) + q-chain + mask sniff on side stream
    cudaEventRecord(evFork, 0);
    cudaStreamWaitEvent(sQ, evFork, 0);
    k_gram_simt<<<160, 256, 0, sQ>>>(Wk);
    cudaEventRecord(evG, sQ);
    k_detect_mask<<<1, 256, 0, sQ>>>((const unsigned int*)mask);
    k_qproj_gemm<<<64, 256, 0, sQ>>>(target, Wq);
    k_qnorm<<<64, 256, 0, sQ>>>(qw, kw);
    k_qtilde_gemm<<<64, 256, 0, sQ>>>(Wk);
    cudaEventRecord(evJoin, sQ);

    // main chain
    k_tofp16<<<2048, 256>>>(hist, hH, BB * SS * DD / 4);
    cudaStreamWaitEvent(0, evG, 0);
    k_knorm_tri<<<BB * NKVH * 4 * 2, 256, KN_SMEM>>>();

    // join: scores needs g_qt + g_mask_mode (sQ) and g_sumsq2 (main)
    cudaStreamWaitEvent(0, evJoin, 0);
    k_scores<<<256, 256>>>(hist, mask);
    k_softmax<<<64, 256>>>(out);
    k_ctx<<<256, 512>>>(hist);
    k_out<<<64, 256>>>(Wv, out);
}